// round 7
// baseline (speedup 1.0000x reference)
#include <cuda_runtime.h>

#define BS     8
#define NPTS   16384
#define C      32
#define K      256
#define KNN_K  16

typedef unsigned long long ull;

// -------------------- f32x2 packed helpers (Blackwell) --------------------
__device__ __forceinline__ ull pack2(float a, float b) {
    ull r; asm("mov.b64 %0, {%1,%2};" : "=l"(r) : "f"(a), "f"(b)); return r;
}
__device__ __forceinline__ void unpack2(ull v, float& lo, float& hi) {
    asm("mov.b64 {%0,%1}, %2;" : "=f"(lo), "=f"(hi) : "l"(v));
}
__device__ __forceinline__ void fma2(ull& d, ull a, ull b) {
    asm("fma.rn.f32x2 %0, %1, %2, %0;" : "+l"(d) : "l"(a), "l"(b));
}
__device__ __forceinline__ ull add2(ull a, ull b) {
    ull r; asm("add.rn.f32x2 %0, %1, %2;" : "=l"(r) : "l"(a), "l"(b)); return r;
}

// -------------------- scratch (static device arrays) --------------------
__device__ ull   g_part2[16 * 128 * 256];   // [(b*2+kblk)][rowblk][item]
__device__ float g_kp[BS * K * 3];

// ---------------------------------------------------------------------------
// Kernel 1 (frozen at 74.2us): FFMA2 register-tiled GEMM + exp epilogue.
// s[b,n,k] = f[b,n,:]·Wreg[0:32,k]  (pooling-head columns cancel in the
// softmax over n). Block: 128 rows x 128 k. Thread: 8 rows x 4 k-pairs.
// ---------------------------------------------------------------------------
#define SA_STRIDE 260

__global__ void __launch_bounds__(256, 2) regress_gemm_kernel(
    const float* __restrict__ f, const float* __restrict__ posg,
    const float* __restrict__ Wreg)
{
    const int rowblk = blockIdx.x, kblk = blockIdx.y, b = blockIdx.z;
    const int t = threadIdx.x;
    const int tr = t & 15, tk = t >> 4;

    __shared__ float sA[32 * SA_STRIDE];
    __shared__ ull   sW[32 * 64];
    __shared__ float sP[128 * 6];

    const float4* f4 = (const float4*)(f + ((size_t)b * NPTS + rowblk * 128) * C);
#pragma unroll
    for (int i = 0; i < 4; ++i) {
        const int idx = t + i * 256;
        const int r = idx >> 3, c4 = idx & 7;
        const float4 v = f4[idx];
        const int wb = ((r & 7) >> 1) * 64 + (r >> 3) * 4 + (r & 1) * 2;
        ((float2*)(sA + (c4 * 4 + 0) * SA_STRIDE + wb))[0] = make_float2(v.x, v.x);
        ((float2*)(sA + (c4 * 4 + 1) * SA_STRIDE + wb))[0] = make_float2(v.y, v.y);
        ((float2*)(sA + (c4 * 4 + 2) * SA_STRIDE + wb))[0] = make_float2(v.z, v.z);
        ((float2*)(sA + (c4 * 4 + 3) * SA_STRIDE + wb))[0] = make_float2(v.w, v.w);
    }
    for (int i = t; i < 32 * 64; i += 256) {
        const int c = i >> 6, jj = i & 63;
        const float* wp = Wreg + c * K + kblk * 128 + 2 * jj;
        sW[i] = pack2(wp[0], wp[1]);
    }
    const float* pb = posg + ((size_t)b * NPTS + rowblk * 128) * 3;
    for (int i = t; i < 128 * 3; i += 256) {
        const int r = i / 3, d = i - r * 3;
        const float v = pb[i];
        sP[r * 6 + 2 * d] = v; sP[r * 6 + 2 * d + 1] = v;
    }
    __syncthreads();

    ull acc[8][4];
#pragma unroll
    for (int r = 0; r < 8; ++r)
#pragma unroll
        for (int j = 0; j < 4; ++j) acc[r][j] = 0ull;

    const ulonglong2* A2 = (const ulonglong2*)sA;
    const ulonglong2* W2 = (const ulonglong2*)sW;

#pragma unroll 4
    for (int c = 0; c < 32; ++c) {
        const ulonglong2 a0 = A2[c * 65 + 0 * 16 + tr];
        const ulonglong2 a1 = A2[c * 65 + 1 * 16 + tr];
        const ulonglong2 a2 = A2[c * 65 + 2 * 16 + tr];
        const ulonglong2 a3 = A2[c * 65 + 3 * 16 + tr];
        const ulonglong2 w0 = W2[c * 32 + tk * 2 + 0];
        const ulonglong2 w1 = W2[c * 32 + tk * 2 + 1];
        fma2(acc[0][0], a0.x, w0.x); fma2(acc[0][1], a0.x, w0.y);
        fma2(acc[0][2], a0.x, w1.x); fma2(acc[0][3], a0.x, w1.y);
        fma2(acc[1][0], a0.y, w0.x); fma2(acc[1][1], a0.y, w0.y);
        fma2(acc[1][2], a0.y, w1.x); fma2(acc[1][3], a0.y, w1.y);
        fma2(acc[2][0], a1.x, w0.x); fma2(acc[2][1], a1.x, w0.y);
        fma2(acc[2][2], a1.x, w1.x); fma2(acc[2][3], a1.x, w1.y);
        fma2(acc[3][0], a1.y, w0.x); fma2(acc[3][1], a1.y, w0.y);
        fma2(acc[3][2], a1.y, w1.x); fma2(acc[3][3], a1.y, w1.y);
        fma2(acc[4][0], a2.x, w0.x); fma2(acc[4][1], a2.x, w0.y);
        fma2(acc[4][2], a2.x, w1.x); fma2(acc[4][3], a2.x, w1.y);
        fma2(acc[5][0], a2.y, w0.x); fma2(acc[5][1], a2.y, w0.y);
        fma2(acc[5][2], a2.y, w1.x); fma2(acc[5][3], a2.y, w1.y);
        fma2(acc[6][0], a3.x, w0.x); fma2(acc[6][1], a3.x, w0.y);
        fma2(acc[6][2], a3.x, w1.x); fma2(acc[6][3], a3.x, w1.y);
        fma2(acc[7][0], a3.y, w0.x); fma2(acc[7][1], a3.y, w0.y);
        fma2(acc[7][2], a3.y, w1.x); fma2(acc[7][3], a3.y, w1.y);
    }

    ull Qz[4], Qx[4], Qy[4], Qw[4];
#pragma unroll
    for (int j = 0; j < 4; ++j) { Qz[j] = 0; Qx[j] = 0; Qy[j] = 0; Qw[j] = 0; }
    const ull ONE2 = pack2(1.0f, 1.0f);
#pragma unroll
    for (int r = 0; r < 8; ++r) {
        const int rg = tr * 8 + r;
        const ull px2 = *(const ull*)(sP + rg * 6 + 0);
        const ull py2 = *(const ull*)(sP + rg * 6 + 2);
        const ull pz2 = *(const ull*)(sP + rg * 6 + 4);
#pragma unroll
        for (int j = 0; j < 4; ++j) {
            float lo, hi; unpack2(acc[r][j], lo, hi);
            const ull e2 = pack2(__expf(lo), __expf(hi));
            fma2(Qz[j], e2, ONE2);
            fma2(Qx[j], e2, px2);
            fma2(Qy[j], e2, py2);
            fma2(Qw[j], e2, pz2);
        }
    }

    __syncthreads();
    ull* sred = (ull*)sA;
#pragma unroll
    for (int j = 0; j < 4; ++j) {
        const int base = tr * 260 + (tk * 4 + j) * 4;
        sred[base + 0] = Qz[j]; sred[base + 1] = Qx[j];
        sred[base + 2] = Qy[j]; sred[base + 3] = Qw[j];
    }
    __syncthreads();
    ull s = sred[t];
#pragma unroll
    for (int i = 1; i < 16; ++i) s = add2(s, sred[i * 260 + t]);
    g_part2[((size_t)(b * 2 + kblk) * 128 + rowblk) * 256 + t] = s;
}

// ---------------------------------------------------------------------------
// Kernel 2: merge rowblk partials -> keypoints. 16 blocks x 256 threads.
// ---------------------------------------------------------------------------
__global__ void merge_kp_kernel()
{
    const int bf = blockIdx.x;
    const int t = threadIdx.x;
    const ull* base = g_part2 + (size_t)bf * 128 * 256 + t;
    ull s = 0;
#pragma unroll 8
    for (int rb = 0; rb < 128; ++rb) s = add2(s, base[(size_t)rb * 256]);
    __shared__ ull red[256];
    red[t] = s;
    __syncthreads();
    if (t < 128) {
        const int jj = t >> 1, half = t & 1;
        float2 vz = *(float2*)&red[jj * 4 + 0];
        float2 vx = *(float2*)&red[jj * 4 + 1];
        float2 vy = *(float2*)&red[jj * 4 + 2];
        float2 vw = *(float2*)&red[jj * 4 + 3];
        const float Z  = half ? vz.y : vz.x;
        const float wx = half ? vx.y : vx.x;
        const float wy = half ? vy.y : vy.x;
        const float wz = half ? vw.y : vw.x;
        const float inv = 1.0f / Z;
        const int b = bf >> 1, kblk = bf & 1;
        const int kp = (b * K + kblk * 128 + t);
        g_kp[kp * 3 + 0] = wx * inv;
        g_kp[kp * 3 + 1] = wy * inv;
        g_kp[kp * 3 + 2] = wz * inv;
    }
}

// ---------------------------------------------------------------------------
// Kernel 3: split-scan KNN. Block = 8 queries x 4 scan-warps (1024 thr).
// Each scan-warp finds the exact top-16 (lex (d,idx), matching top_k ties)
// of its 4096-point slice with the warp-sorted-list trick; the 4 sorted
// lists are merged by one warp per query with early-break inserts.
// 4x shorter serial chains + 14 warps/SMSP -> latency actually hidden.
// ---------------------------------------------------------------------------
#define QPB 8   // queries per block

__global__ void __launch_bounds__(32 * QPB * 4) knn_extract_kernel(
    const float* __restrict__ f, const float* __restrict__ posg,
    const float* __restrict__ WE, float* __restrict__ out)
{
    __shared__ float sWE[C * C];
    __shared__ float sd[QPB * 64];   // [query][chunk*16 + e]
    __shared__ int   si[QPB * 64];

    const int t = threadIdx.x;
    const int w = t >> 5, lane = t & 31;
    const int q = w >> 2, sw = w & 3;          // query slot, scan-chunk
    for (int i = t; i < C * C; i += 32 * QPB * 4) sWE[i] = WE[i];

    const int pair = blockIdx.x * QPB + q;     // QPB | 256 -> block shares b
    const int b = pair >> 8;

    const float kx = g_kp[pair * 3 + 0];
    const float ky = g_kp[pair * 3 + 1];
    const float kz = g_kp[pair * 3 + 2];
    const float4* pb4 = (const float4*)(posg + (size_t)b * NPTS * 3);

    float bd = 3.4e38f;   int bi = 0x7fffffff;   // warp-sorted list
    float td = 3.4e38f;   int ti = 0x7fffffff;   // lane-15 (16th smallest)

    // ---- scan this warp's 4096-point slice (32 iterations, 4 pts/lane)
    for (int it = 0; it < 32; ++it) {
        const int p = sw * 1024 + it * 32 + lane;   // point group 4p..4p+3
        const float4 g0 = pb4[3 * p + 0];
        const float4 g1 = pb4[3 * p + 1];
        const float4 g2 = pb4[3 * p + 2];
        float dx, dy, dz;
        dx = g0.x - kx; dy = g0.y - ky; dz = g0.z - kz;
        const float d0 = fmaf(dx, dx, fmaf(dy, dy, dz * dz));
        dx = g0.w - kx; dy = g1.x - ky; dz = g1.y - kz;
        const float d1 = fmaf(dx, dx, fmaf(dy, dy, dz * dz));
        dx = g1.z - kx; dy = g1.w - ky; dz = g2.x - kz;
        const float d2 = fmaf(dx, dx, fmaf(dy, dy, dz * dz));
        dx = g2.y - kx; dy = g2.z - ky; dz = g2.w - kz;
        const float d3 = fmaf(dx, dx, fmaf(dy, dy, dz * dz));
        const float dmin = fminf(fminf(d0, d1), fminf(d2, d3));

        unsigned m = __ballot_sync(0xffffffffu, dmin <= td);
        while (m) {
            const int src = __ffs(m) - 1; m &= m - 1;
            float dc4[4];
            dc4[0] = __shfl_sync(0xffffffffu, d0, src);
            dc4[1] = __shfl_sync(0xffffffffu, d1, src);
            dc4[2] = __shfl_sync(0xffffffffu, d2, src);
            dc4[3] = __shfl_sync(0xffffffffu, d3, src);
            const int idxb = 4 * (sw * 1024 + it * 32 + src);
#pragma unroll
            for (int jc = 0; jc < 4; ++jc) {
                const float dc = dc4[jc];
                const int   ic = idxb + jc;
                if (dc < td || (dc == td && ic < ti)) {
                    float pd = __shfl_up_sync(0xffffffffu, bd, 1);
                    int   pi = __shfl_up_sync(0xffffffffu, bi, 1);
                    if (lane == 0) { pd = -3.4e38f; pi = -1; }
                    const bool disp = (dc < bd) || (dc == bd && ic < bi);
                    if (disp) {
                        const bool tp = (pd > dc) || (pd == dc && pi > ic);
                        bd = tp ? pd : dc;
                        bi = tp ? pi : ic;
                    }
                }
            }
            td = __shfl_sync(0xffffffffu, bd, KNN_K - 1);
            ti = __shfl_sync(0xffffffffu, bi, KNN_K - 1);
        }
    }

    // ---- publish per-chunk sorted top-16
    if (lane < KNN_K) {
        sd[q * 64 + sw * 16 + lane] = bd;
        si[q * 64 + sw * 16 + lane] = bi;
    }
    __syncthreads();

    // ---- merge (warps 0..QPB-1, one per query) + gather + GEMV
    if (w < QPB) {
        const int mq = w;
        const int mpair = blockIdx.x * QPB + mq;
        // init list from chunk 0
        float md = 3.4e38f; int mi = 0x7fffffff;
        if (lane < KNN_K) { md = sd[mq * 64 + lane]; mi = si[mq * 64 + lane]; }
        float mtd = __shfl_sync(0xffffffffu, md, KNN_K - 1);
        int   mti = __shfl_sync(0xffffffffu, mi, KNN_K - 1);
#pragma unroll
        for (int chunk = 1; chunk < 4; ++chunk) {
            for (int e = 0; e < KNN_K; ++e) {
                const float dc = sd[mq * 64 + chunk * 16 + e];  // broadcast
                const int   ic = si[mq * 64 + chunk * 16 + e];
                if (!(dc < mtd || (dc == mtd && ic < mti))) break;  // sorted
                float pd = __shfl_up_sync(0xffffffffu, md, 1);
                int   pi = __shfl_up_sync(0xffffffffu, mi, 1);
                if (lane == 0) { pd = -3.4e38f; pi = -1; }
                const bool disp = (dc < md) || (dc == md && ic < mi);
                if (disp) {
                    const bool tp = (pd > dc) || (pd == dc && pi > ic);
                    md = tp ? pd : dc;
                    mi = tp ? pi : ic;
                }
                mtd = __shfl_sync(0xffffffffu, md, KNN_K - 1);
                mti = __shfl_sync(0xffffffffu, mi, KNN_K - 1);
            }
        }

        // gather features of 16 nearest (lanes 0..15), mean, GEMV
        const int mb = mpair >> 8;
        const float* fbase = f + (size_t)mb * NPTS * C;
        float acc = 0.f;
#pragma unroll
        for (int r = 0; r < KNN_K; ++r) {
            const int id = __shfl_sync(0xffffffffu, mi, r);
            acc += fbase[(size_t)id * C + lane];
        }
        acc *= (1.0f / KNN_K);

        float o = 0.f;
#pragma unroll
        for (int c = 0; c < C; ++c)
            o = fmaf(__shfl_sync(0xffffffffu, acc, c), sWE[c * C + lane], o);

        out[(size_t)mpair * C + lane] = o;
    }
}

// ---------------------------------------------------------------------------
// Inputs: feature, pos, W_pool (dead code — softmax over n cancels the
// per-(b,k)-constant pooled columns), W_regress, W_extract, bs.
// ---------------------------------------------------------------------------
extern "C" void kernel_launch(void* const* d_in, const int* in_sizes, int n_in,
                              void* d_out, int out_size)
{
    (void)in_sizes; (void)n_in; (void)out_size;
    const float* f    = (const float*)d_in[0];
    const float* pos  = (const float*)d_in[1];
    const float* Wreg = (const float*)d_in[3];
    const float* WE   = (const float*)d_in[4];
    float* out = (float*)d_out;

    dim3 g1(NPTS / 128, 2, BS);
    regress_gemm_kernel<<<g1, 256>>>(f, pos, Wreg);
    merge_kp_kernel<<<16, 256>>>();
    knn_extract_kernel<<<BS * K / QPB, 32 * QPB * 4>>>(f, pos, WE, out);
}

// round 8
// speedup vs baseline: 1.2307x; 1.2307x over previous
#include <cuda_runtime.h>

#define BS     8
#define NPTS   16384
#define C      32
#define K      256
#define KNN_K  16

typedef unsigned long long ull;

// -------------------- f32x2 packed helpers (Blackwell) --------------------
__device__ __forceinline__ ull pack2(float a, float b) {
    ull r; asm("mov.b64 %0, {%1,%2};" : "=l"(r) : "f"(a), "f"(b)); return r;
}
__device__ __forceinline__ void unpack2(ull v, float& lo, float& hi) {
    asm("mov.b64 {%0,%1}, %2;" : "=f"(lo), "=f"(hi) : "l"(v));
}
__device__ __forceinline__ void fma2(ull& d, ull a, ull b) {
    asm("fma.rn.f32x2 %0, %1, %2, %0;" : "+l"(d) : "l"(a), "l"(b));
}
__device__ __forceinline__ ull add2(ull a, ull b) {
    ull r; asm("add.rn.f32x2 %0, %1, %2;" : "=l"(r) : "l"(a), "l"(b)); return r;
}

// -------------------- scratch (static device arrays) --------------------
__device__ ull   g_part2[16 * 128 * 256];   // [(b*2+kblk)][rowblk][item]
__device__ float g_kp[BS * K * 3];

// ---------------------------------------------------------------------------
// Kernel 1 (frozen at 74.2us): FFMA2 register-tiled GEMM + exp epilogue.
// s[b,n,k] = f[b,n,:]·Wreg[0:32,k]  (pooling-head columns cancel in the
// softmax over n). Block: 128 rows x 128 k. Thread: 8 rows x 4 k-pairs.
// ---------------------------------------------------------------------------
#define SA_STRIDE 260

__global__ void __launch_bounds__(256, 2) regress_gemm_kernel(
    const float* __restrict__ f, const float* __restrict__ posg,
    const float* __restrict__ Wreg)
{
    const int rowblk = blockIdx.x, kblk = blockIdx.y, b = blockIdx.z;
    const int t = threadIdx.x;
    const int tr = t & 15, tk = t >> 4;

    __shared__ float sA[32 * SA_STRIDE];
    __shared__ ull   sW[32 * 64];
    __shared__ float sP[128 * 6];

    const float4* f4 = (const float4*)(f + ((size_t)b * NPTS + rowblk * 128) * C);
#pragma unroll
    for (int i = 0; i < 4; ++i) {
        const int idx = t + i * 256;
        const int r = idx >> 3, c4 = idx & 7;
        const float4 v = f4[idx];
        const int wb = ((r & 7) >> 1) * 64 + (r >> 3) * 4 + (r & 1) * 2;
        ((float2*)(sA + (c4 * 4 + 0) * SA_STRIDE + wb))[0] = make_float2(v.x, v.x);
        ((float2*)(sA + (c4 * 4 + 1) * SA_STRIDE + wb))[0] = make_float2(v.y, v.y);
        ((float2*)(sA + (c4 * 4 + 2) * SA_STRIDE + wb))[0] = make_float2(v.z, v.z);
        ((float2*)(sA + (c4 * 4 + 3) * SA_STRIDE + wb))[0] = make_float2(v.w, v.w);
    }
    for (int i = t; i < 32 * 64; i += 256) {
        const int c = i >> 6, jj = i & 63;
        const float* wp = Wreg + c * K + kblk * 128 + 2 * jj;
        sW[i] = pack2(wp[0], wp[1]);
    }
    const float* pb = posg + ((size_t)b * NPTS + rowblk * 128) * 3;
    for (int i = t; i < 128 * 3; i += 256) {
        const int r = i / 3, d = i - r * 3;
        const float v = pb[i];
        sP[r * 6 + 2 * d] = v; sP[r * 6 + 2 * d + 1] = v;
    }
    __syncthreads();

    ull acc[8][4];
#pragma unroll
    for (int r = 0; r < 8; ++r)
#pragma unroll
        for (int j = 0; j < 4; ++j) acc[r][j] = 0ull;

    const ulonglong2* A2 = (const ulonglong2*)sA;
    const ulonglong2* W2 = (const ulonglong2*)sW;

#pragma unroll 4
    for (int c = 0; c < 32; ++c) {
        const ulonglong2 a0 = A2[c * 65 + 0 * 16 + tr];
        const ulonglong2 a1 = A2[c * 65 + 1 * 16 + tr];
        const ulonglong2 a2 = A2[c * 65 + 2 * 16 + tr];
        const ulonglong2 a3 = A2[c * 65 + 3 * 16 + tr];
        const ulonglong2 w0 = W2[c * 32 + tk * 2 + 0];
        const ulonglong2 w1 = W2[c * 32 + tk * 2 + 1];
        fma2(acc[0][0], a0.x, w0.x); fma2(acc[0][1], a0.x, w0.y);
        fma2(acc[0][2], a0.x, w1.x); fma2(acc[0][3], a0.x, w1.y);
        fma2(acc[1][0], a0.y, w0.x); fma2(acc[1][1], a0.y, w0.y);
        fma2(acc[1][2], a0.y, w1.x); fma2(acc[1][3], a0.y, w1.y);
        fma2(acc[2][0], a1.x, w0.x); fma2(acc[2][1], a1.x, w0.y);
        fma2(acc[2][2], a1.x, w1.x); fma2(acc[2][3], a1.x, w1.y);
        fma2(acc[3][0], a1.y, w0.x); fma2(acc[3][1], a1.y, w0.y);
        fma2(acc[3][2], a1.y, w1.x); fma2(acc[3][3], a1.y, w1.y);
        fma2(acc[4][0], a2.x, w0.x); fma2(acc[4][1], a2.x, w0.y);
        fma2(acc[4][2], a2.x, w1.x); fma2(acc[4][3], a2.x, w1.y);
        fma2(acc[5][0], a2.y, w0.x); fma2(acc[5][1], a2.y, w0.y);
        fma2(acc[5][2], a2.y, w1.x); fma2(acc[5][3], a2.y, w1.y);
        fma2(acc[6][0], a3.x, w0.x); fma2(acc[6][1], a3.x, w0.y);
        fma2(acc[6][2], a3.x, w1.x); fma2(acc[6][3], a3.x, w1.y);
        fma2(acc[7][0], a3.y, w0.x); fma2(acc[7][1], a3.y, w0.y);
        fma2(acc[7][2], a3.y, w1.x); fma2(acc[7][3], a3.y, w1.y);
    }

    ull Qz[4], Qx[4], Qy[4], Qw[4];
#pragma unroll
    for (int j = 0; j < 4; ++j) { Qz[j] = 0; Qx[j] = 0; Qy[j] = 0; Qw[j] = 0; }
    const ull ONE2 = pack2(1.0f, 1.0f);
#pragma unroll
    for (int r = 0; r < 8; ++r) {
        const int rg = tr * 8 + r;
        const ull px2 = *(const ull*)(sP + rg * 6 + 0);
        const ull py2 = *(const ull*)(sP + rg * 6 + 2);
        const ull pz2 = *(const ull*)(sP + rg * 6 + 4);
#pragma unroll
        for (int j = 0; j < 4; ++j) {
            float lo, hi; unpack2(acc[r][j], lo, hi);
            const ull e2 = pack2(__expf(lo), __expf(hi));
            fma2(Qz[j], e2, ONE2);
            fma2(Qx[j], e2, px2);
            fma2(Qy[j], e2, py2);
            fma2(Qw[j], e2, pz2);
        }
    }

    __syncthreads();
    ull* sred = (ull*)sA;
#pragma unroll
    for (int j = 0; j < 4; ++j) {
        const int base = tr * 260 + (tk * 4 + j) * 4;
        sred[base + 0] = Qz[j]; sred[base + 1] = Qx[j];
        sred[base + 2] = Qy[j]; sred[base + 3] = Qw[j];
    }
    __syncthreads();
    ull s = sred[t];
#pragma unroll
    for (int i = 1; i < 16; ++i) s = add2(s, sred[i * 260 + t]);
    g_part2[((size_t)(b * 2 + kblk) * 128 + rowblk) * 256 + t] = s;
}

// ---------------------------------------------------------------------------
// Kernel 2: merge rowblk partials -> keypoints. 16 blocks x 256 threads.
// ---------------------------------------------------------------------------
__global__ void merge_kp_kernel()
{
    const int bf = blockIdx.x;
    const int t = threadIdx.x;
    const ull* base = g_part2 + (size_t)bf * 128 * 256 + t;
    ull s = 0;
#pragma unroll 8
    for (int rb = 0; rb < 128; ++rb) s = add2(s, base[(size_t)rb * 256]);
    __shared__ ull red[256];
    red[t] = s;
    __syncthreads();
    if (t < 128) {
        const int jj = t >> 1, half = t & 1;
        float2 vz = *(float2*)&red[jj * 4 + 0];
        float2 vx = *(float2*)&red[jj * 4 + 1];
        float2 vy = *(float2*)&red[jj * 4 + 2];
        float2 vw = *(float2*)&red[jj * 4 + 3];
        const float Z  = half ? vz.y : vz.x;
        const float wx = half ? vx.y : vx.x;
        const float wy = half ? vy.y : vy.x;
        const float wz = half ? vw.y : vw.x;
        const float inv = 1.0f / Z;
        const int b = bf >> 1, kblk = bf & 1;
        const int kp = (b * K + kblk * 128 + t);
        g_kp[kp * 3 + 0] = wx * inv;
        g_kp[kp * 3 + 1] = wy * inv;
        g_kp[kp * 3 + 2] = wz * inv;
    }
}

// ---------------------------------------------------------------------------
// Kernel 3: threshold two-pass KNN. One warp per (b,k), 8 warps/block.
// Pass 1: per-lane running mins (no cross-lane ops) -> bitonic(32) ->
//         T = 16th-smallest lane-min (>= true 16th-smallest: the 16 smallest
//         lane-minima are values of 16 distinct points).
// Pass 2: compact all points with d2 <= T (expected ~22) via ballot+popc.
// Pass 3: exact lex (d, idx) selection among candidates (bitonic + rare
//         early-break inserts). Matches jax top_k tie-breaking exactly.
// ---------------------------------------------------------------------------
#define QPB   8
#define CCAP  512

__global__ void __launch_bounds__(32 * QPB) knn_extract_kernel(
    const float* __restrict__ f, const float* __restrict__ posg,
    const float* __restrict__ WE, float* __restrict__ out)
{
    __shared__ float sWE[C * C];
    __shared__ float scd[QPB][CCAP];
    __shared__ int   sci[QPB][CCAP];

    const int t = threadIdx.x;
    const int w = t >> 5, lane = t & 31;
    for (int i = t; i < C * C; i += 32 * QPB) sWE[i] = WE[i];
    __syncthreads();   // only block barrier; warps free-run after

    const int pair = blockIdx.x * QPB + w;     // QPB | 256 -> block shares b
    const int b = pair >> 8;

    const float kx = g_kp[pair * 3 + 0];
    const float ky = g_kp[pair * 3 + 1];
    const float kz = g_kp[pair * 3 + 2];
    const float4* pb4 = (const float4*)(posg + (size_t)b * NPTS * 3);

    const float INF = 3.4e38f;

    // ---- pass 1: per-lane running mins over 512 points (4 indep chains)
    float m0 = INF, m1 = INF, m2 = INF, m3 = INF;
    for (int it = 0; it < NPTS / 128; ++it) {
        const int p = it * 32 + lane;
        const float4 g0 = pb4[3 * p + 0];
        const float4 g1 = pb4[3 * p + 1];
        const float4 g2 = pb4[3 * p + 2];
        float dx, dy, dz;
        dx = g0.x - kx; dy = g0.y - ky; dz = g0.z - kz;
        m0 = fminf(m0, fmaf(dx, dx, fmaf(dy, dy, dz * dz)));
        dx = g0.w - kx; dy = g1.x - ky; dz = g1.y - kz;
        m1 = fminf(m1, fmaf(dx, dx, fmaf(dy, dy, dz * dz)));
        dx = g1.z - kx; dy = g1.w - ky; dz = g2.x - kz;
        m2 = fminf(m2, fmaf(dx, dx, fmaf(dy, dy, dz * dz)));
        dx = g2.y - kx; dy = g2.z - ky; dz = g2.w - kz;
        m3 = fminf(m3, fmaf(dx, dx, fmaf(dy, dy, dz * dz)));
    }
    // bitonic sort 32 lane-minima ascending; T = lane 15
    float v = fminf(fminf(m0, m1), fminf(m2, m3));
#pragma unroll
    for (int k = 2; k <= 32; k <<= 1) {
#pragma unroll
        for (int j = k >> 1; j > 0; j >>= 1) {
            const float o = __shfl_xor_sync(0xffffffffu, v, j);
            const bool asc = ((lane & k) == 0);
            const bool keepmin = (((lane & j) == 0) == asc);
            v = keepmin ? fminf(v, o) : fmaxf(v, o);
        }
    }
    const float T = __shfl_sync(0xffffffffu, v, KNN_K - 1);

    // ---- pass 2: compact candidates with d2 <= T (loads are L1-hot)
    const unsigned lmask = (1u << lane) - 1u;
    int cnt = 0;
    for (int it = 0; it < NPTS / 128; ++it) {
        const int p = it * 32 + lane;
        const float4 g0 = pb4[3 * p + 0];
        const float4 g1 = pb4[3 * p + 1];
        const float4 g2 = pb4[3 * p + 2];
        float dx, dy, dz;
        dx = g0.x - kx; dy = g0.y - ky; dz = g0.z - kz;
        const float d0 = fmaf(dx, dx, fmaf(dy, dy, dz * dz));
        dx = g0.w - kx; dy = g1.x - ky; dz = g1.y - kz;
        const float d1 = fmaf(dx, dx, fmaf(dy, dy, dz * dz));
        dx = g1.z - kx; dy = g1.w - ky; dz = g2.x - kz;
        const float d2 = fmaf(dx, dx, fmaf(dy, dy, dz * dz));
        dx = g2.y - kx; dy = g2.z - ky; dz = g2.w - kz;
        const float d3 = fmaf(dx, dx, fmaf(dy, dy, dz * dz));
        // quick skip when no lane qualifies (common case: 1 ballot/iter)
        const float dmin = fminf(fminf(d0, d1), fminf(d2, d3));
        if (__ballot_sync(0xffffffffu, dmin <= T) == 0u) continue;
        const int pi4 = 4 * p;
        {
            const unsigned mm = __ballot_sync(0xffffffffu, d0 <= T);
            if (d0 <= T) { const int o = cnt + __popc(mm & lmask);
                if (o < CCAP) { scd[w][o] = d0; sci[w][o] = pi4 + 0; } }
            cnt += __popc(mm);
        }
        {
            const unsigned mm = __ballot_sync(0xffffffffu, d1 <= T);
            if (d1 <= T) { const int o = cnt + __popc(mm & lmask);
                if (o < CCAP) { scd[w][o] = d1; sci[w][o] = pi4 + 1; } }
            cnt += __popc(mm);
        }
        {
            const unsigned mm = __ballot_sync(0xffffffffu, d2 <= T);
            if (d2 <= T) { const int o = cnt + __popc(mm & lmask);
                if (o < CCAP) { scd[w][o] = d2; sci[w][o] = pi4 + 2; } }
            cnt += __popc(mm);
        }
        {
            const unsigned mm = __ballot_sync(0xffffffffu, d3 <= T);
            if (d3 <= T) { const int o = cnt + __popc(mm & lmask);
                if (o < CCAP) { scd[w][o] = d3; sci[w][o] = pi4 + 3; } }
            cnt += __popc(mm);
        }
    }
    if (cnt > CCAP) cnt = CCAP;
    __syncwarp();

    // ---- pass 3: exact selection. Group 0: lex bitonic sort of 32.
    float md; int mi;
    {
        md = (lane < cnt) ? scd[w][lane] : INF;
        mi = (lane < cnt) ? sci[w][lane] : 0x7fffffff;
#pragma unroll
        for (int k = 2; k <= 32; k <<= 1) {
#pragma unroll
            for (int j = k >> 1; j > 0; j >>= 1) {
                const float od = __shfl_xor_sync(0xffffffffu, md, j);
                const int   oi = __shfl_xor_sync(0xffffffffu, mi, j);
                const bool asc = ((lane & k) == 0);
                const bool low = ((lane & j) == 0);
                const bool oLess = (od < md) || (od == md && oi < mi);
                const bool takeOther = (low == asc) ? oLess : !oLess;
                if (takeOther) { md = od; mi = oi; }
            }
        }
    }
    float mtd = __shfl_sync(0xffffffffu, md, KNN_K - 1);
    int   mti = __shfl_sync(0xffffffffu, mi, KNN_K - 1);

    // rare extra groups: sort, then early-break inserts
    for (int base0 = 32; base0 < cnt; base0 += 32) {
        const int jj = base0 + lane;
        float cd2 = (jj < cnt) ? scd[w][jj] : INF;
        int   ci2 = (jj < cnt) ? sci[w][jj] : 0x7fffffff;
#pragma unroll
        for (int k = 2; k <= 32; k <<= 1) {
#pragma unroll
            for (int j = k >> 1; j > 0; j >>= 1) {
                const float od = __shfl_xor_sync(0xffffffffu, cd2, j);
                const int   oi = __shfl_xor_sync(0xffffffffu, ci2, j);
                const bool asc = ((lane & k) == 0);
                const bool low = ((lane & j) == 0);
                const bool oLess = (od < cd2) || (od == cd2 && oi < ci2);
                const bool takeOther = (low == asc) ? oLess : !oLess;
                if (takeOther) { cd2 = od; ci2 = oi; }
            }
        }
        for (int e = 0; e < 32; ++e) {
            const float dc = __shfl_sync(0xffffffffu, cd2, e);
            const int   ic = __shfl_sync(0xffffffffu, ci2, e);
            if (!(dc < mtd || (dc == mtd && ic < mti))) break;  // sorted input
            float pd = __shfl_up_sync(0xffffffffu, md, 1);
            int   pi = __shfl_up_sync(0xffffffffu, mi, 1);
            if (lane == 0) { pd = -INF; pi = -1; }
            const bool disp = (dc < md) || (dc == md && ic < mi);
            if (disp) {
                const bool tp = (pd > dc) || (pd == dc && pi > ic);
                md = tp ? pd : dc;
                mi = tp ? pi : ic;
            }
            mtd = __shfl_sync(0xffffffffu, md, KNN_K - 1);
            mti = __shfl_sync(0xffffffffu, mi, KNN_K - 1);
        }
    }

    // ---- gather features of 16 nearest (lanes 0..15), mean, GEMV
    const float* fbase = f + (size_t)b * NPTS * C;
    float acc = 0.f;
#pragma unroll
    for (int r = 0; r < KNN_K; ++r) {
        const int id = __shfl_sync(0xffffffffu, mi, r);
        acc += fbase[(size_t)id * C + lane];
    }
    acc *= (1.0f / KNN_K);

    float o = 0.f;
#pragma unroll
    for (int c = 0; c < C; ++c)
        o = fmaf(__shfl_sync(0xffffffffu, acc, c), sWE[c * C + lane], o);

    out[(size_t)pair * C + lane] = o;
}

// ---------------------------------------------------------------------------
// Inputs: feature, pos, W_pool (dead code — softmax over n cancels the
// per-(b,k)-constant pooled columns), W_regress, W_extract, bs.
// ---------------------------------------------------------------------------
extern "C" void kernel_launch(void* const* d_in, const int* in_sizes, int n_in,
                              void* d_out, int out_size)
{
    (void)in_sizes; (void)n_in; (void)out_size;
    const float* f    = (const float*)d_in[0];
    const float* pos  = (const float*)d_in[1];
    const float* Wreg = (const float*)d_in[3];
    const float* WE   = (const float*)d_in[4];
    float* out = (float*)d_out;

    dim3 g1(NPTS / 128, 2, BS);
    regress_gemm_kernel<<<g1, 256>>>(f, pos, Wreg);
    merge_kp_kernel<<<16, 256>>>();
    knn_extract_kernel<<<BS * K / QPB, 32 * QPB>>>(f, pos, WE, out);
}